// round 17
// baseline (speedup 1.0000x reference)
#include <cuda_runtime.h>

#define NP     32768
#define HIDN   100
#define NSTEPS 100

typedef unsigned long long u64;

__device__ __forceinline__ u64 pk2(float lo, float hi) {
    u64 r; asm("mov.b64 %0, {%1, %2};" : "=l"(r) : "f"(lo), "f"(hi)); return r;
}
__device__ __forceinline__ void upk2(u64 v, float& lo, float& hi) {
    asm("mov.b64 {%0, %1}, %2;" : "=f"(lo), "=f"(hi) : "l"(v));
}
__device__ __forceinline__ u64 fma2(u64 a, u64 b, u64 c) {
    u64 d; asm("fma.rn.f32x2 %0, %1, %2, %3;" : "=l"(d) : "l"(a), "l"(b), "l"(c)); return d;
}
__device__ __forceinline__ u64 mul2(u64 a, u64 b) {
    u64 d; asm("mul.rn.f32x2 %0, %1, %2;" : "=l"(d) : "l"(a), "l"(b)); return d;
}

// ---------------------------------------------------------------------------
// Encoder (unchanged)
// ---------------------------------------------------------------------------
__global__ void __launch_bounds__(128) encoder_kernel(
    const float* __restrict__ x,
    const float* __restrict__ We1, const float* __restrict__ be1,
    const float* __restrict__ We2, const float* __restrict__ be2,
    const float* __restrict__ Wmu, const float* __restrict__ bmu,
    const float* __restrict__ Wlt, const float* __restrict__ blt,
    float* __restrict__ out)
{
    extern __shared__ float sm[];
    float* sWe2 = sm;             // 10000
    float* sWe1 = sm + 10000;     // 300
    float* sbe1 = sm + 10300;     // 100
    float* sbe2 = sm + 10400;     // 100
    float* sWmu = sm + 10500;     // 200
    float* sWlt = sm + 10700;     // 100
    float* sh1  = sm + 10800;     // 128*101

    const int tid = threadIdx.x;
    for (int i = tid; i < HIDN * HIDN; i += 128) sWe2[i] = We2[i];
    for (int i = tid; i < 3 * HIDN; i += 128)    sWe1[i] = We1[i];
    if (tid < HIDN) {
        sbe1[tid] = be1[tid];
        sbe2[tid] = be2[tid];
        sWlt[tid] = Wlt[tid];
    }
    for (int i = tid; i < HIDN * 2; i += 128) sWmu[i] = Wmu[i];
    __syncthreads();

    const int p = blockIdx.x * 128 + tid;
    const float x0 = x[3 * p + 0];
    const float x1 = x[3 * p + 1];
    const float x2 = x[3 * p + 2];

    float* h1 = sh1 + tid * (HIDN + 1);

    #pragma unroll 4
    for (int k = 0; k < HIDN; k++) {
        float a = sbe1[k];
        a = fmaf(x0, sWe1[k], a);
        a = fmaf(x1, sWe1[HIDN + k], a);
        a = fmaf(x2, sWe1[2 * HIDN + k], a);
        float sig = __fdividef(1.f, 1.f + __expf(-a));
        h1[k] = a * sig;
    }

    float mu0 = bmu[0], mu1 = bmu[1], ltv = blt[0];
    for (int k = 0; k < HIDN; k++) {
        float a = sbe2[k];
        const float* w = sWe2 + k;
        #pragma unroll 4
        for (int j = 0; j < HIDN; j++)
            a = fmaf(h1[j], w[j * HIDN], a);
        float sig = __fdividef(1.f, 1.f + __expf(-a));
        float h2 = a * sig;
        mu0 = fmaf(h2, sWmu[2 * k + 0], mu0);
        mu1 = fmaf(h2, sWmu[2 * k + 1], mu1);
        ltv = fmaf(h2, sWlt[k], ltv);
    }

    out[8 * NP + 2 * p + 0] = mu0;
    out[8 * NP + 2 * p + 1] = mu1;
    out[10 * NP + p]        = ltv;
}

// ---------------------------------------------------------------------------
// Scalar per-point geometry epilogue (identical math to R16).
// ---------------------------------------------------------------------------
__device__ __forceinline__ void geom_update(
    const float J[6][2], const float Bm[6][3],
    float sqdt, float nzx, float nzy, float& z0, float& z1)
{
    float g00 = 0.f, g01 = 0.f, g11 = 0.f;
    float C[3][2];
    C[0][0] = C[0][1] = C[1][0] = C[1][1] = C[2][0] = C[2][1] = 0.f;

    #pragma unroll
    for (int i = 0; i < 6; i++) {
        g00 = fmaf(J[i][0], J[i][0], g00);
        g01 = fmaf(J[i][0], J[i][1], g01);
        g11 = fmaf(J[i][1], J[i][1], g11);
        #pragma unroll
        for (int q = 0; q < 3; q++) {
            C[q][0] = fmaf(Bm[i][q], J[i][0], C[q][0]);
            C[q][1] = fmaf(Bm[i][q], J[i][1], C[q][1]);
        }
    }

    float Dg[2][2][2];
    #pragma unroll
    for (int k = 0; k < 2; k++)
        #pragma unroll
        for (int m = 0; m < 2; m++)
            #pragma unroll
            for (int l = 0; l < 2; l++)
                Dg[k][m][l] = C[k + l][m] + C[m + l][k];

    const float detg = fmaf(g00, g11, -g01 * g01);
    const float rin  = __fdividef(1.f, detg);
    float gi[2][2];
    gi[0][0] =  g11 * rin;
    gi[0][1] = -g01 * rin;
    gi[1][0] = -g01 * rin;
    gi[1][1] =  g00 * rin;

    float Ch[2][2][2];
    #pragma unroll
    for (int i = 0; i < 2; i++)
        #pragma unroll
        for (int k = 0; k < 2; k++)
            #pragma unroll
            for (int l = 0; l < 2; l++) {
                float sacc = 0.f;
                #pragma unroll
                for (int m = 0; m < 2; m++)
                    sacc += gi[i][m] * (Dg[k][m][l] + Dg[l][m][k] - Dg[k][l][m]);
                Ch[i][k][l] = 0.5f * sacc;
            }

    float drift[2];
    #pragma unroll
    for (int i = 0; i < 2; i++) {
        float sacc = 0.f;
        #pragma unroll
        for (int jj = 0; jj < 2; jj++)
            #pragma unroll
            for (int kk = 0; kk < 2; kk++)
                sacc += gi[jj][kk] * Ch[i][jj][kk];
        drift[i] = 0.5f * sacc;
    }

    const float dW0 = sqdt * nzx;
    const float dW1 = sqdt * nzy;
    z0 += drift[0] + gi[0][0] * dW0 + gi[0][1] * dW1;
    z1 += drift[1] + gi[1][0] * dW0 + gi[1][1] * dW1;
}

// ---------------------------------------------------------------------------
// SDE kernel v8: 2 points per thread, f32x2-packed (lane = point).
// 30 accumulator PAIRS; tables pre-duplicated in SMEM as (v,v) 64-bit pairs
// so FFMA2 operands come straight from LDS.128 with no packing MOVs.
// Per-lane arithmetic identical to the scalar v7 kernel.
// ---------------------------------------------------------------------------
__global__ void __launch_bounds__(64) sde_kernel(
    const float* __restrict__ Wd1,  const float* __restrict__ bd1,
    const float* __restrict__ Wdmu, const float* __restrict__ bdmu,
    const float* __restrict__ Wds,  const float* __restrict__ bds,
    const float* __restrict__ b_muz, const float* __restrict__ b_ltz,
    const float* __restrict__ noise,
    float* __restrict__ out)
{
    // sDup[j][0]   = {(u0,u0),(u1,u1)}
    // sDup[j][1+i] = {(wi*u0, wi*u0), (wi*u1, wi*u1)}   i = 0..5
    // sB[j]        = (b,b)
    // tAct/tWa/tWb: scalar tables for the final decoder pass
    __shared__ ulonglong2 sDup[HIDN][7];
    __shared__ u64    sB[HIDN];
    __shared__ float4 tAct[HIDN];
    __shared__ float4 tWa[HIDN];
    __shared__ float2 tWb[HIDN];

    const int tid = threadIdx.x;
    for (int j = tid; j < HIDN; j += 64) {
        float u0 = Wd1[j];
        float u1 = Wd1[HIDN + j];
        float b  = bd1[j];
        float w[6];
        w[0] = Wdmu[3 * j + 0]; w[1] = Wdmu[3 * j + 1]; w[2] = Wdmu[3 * j + 2];
        w[3] = Wds[3 * j + 0];  w[4] = Wds[3 * j + 1];  w[5] = Wds[3 * j + 2];
        ulonglong2 t;
        t.x = pk2(u0, u0); t.y = pk2(u1, u1);
        sDup[j][0] = t;
        #pragma unroll
        for (int i = 0; i < 6; i++) {
            ulonglong2 pi;
            pi.x = pk2(w[i] * u0, w[i] * u0);
            pi.y = pk2(w[i] * u1, w[i] * u1);
            sDup[j][1 + i] = pi;
        }
        sB[j]   = pk2(b, b);
        tAct[j] = make_float4(u0, u1, b, 0.f);
        tWa[j]  = make_float4(w[0], w[1], w[2], w[3]);
        tWb[j]  = make_float2(w[4], w[5]);
    }
    __syncthreads();

    // Two points per thread: A and B (both coalesced within the warp)
    const int pA = blockIdx.x * 128 + tid;
    const int pB = pA + 64;

    float z0A = out[8 * NP + 2 * pA + 0];
    float z1A = out[8 * NP + 2 * pA + 1];
    float z0B = out[8 * NP + 2 * pB + 0];
    float z1B = out[8 * NP + 2 * pB + 1];
    const float sqdtA = sqrtf(__expf(2.f * out[10 * NP + pA]) * (1.0f / NSTEPS));
    const float sqdtB = sqrtf(__expf(2.f * out[10 * NP + pB]) * (1.0f / NSTEPS));

    const float2* __restrict__ noise2 = (const float2*)noise;

    const u64 ONE2   = pk2(1.f, 1.f);
    const u64 TWO2   = pk2(2.f, 2.f);
    const u64 NONE2  = pk2(-1.f, -1.f);
    const u64 NTWO2  = pk2(-2.f, -2.f);

    for (int s = 0; s < NSTEPS; s++) {
        const float2 nzA = noise2[s * NP + pA];
        const float2 nzB = noise2[s * NP + pB];

        u64 zp0 = pk2(z0A, z0B);
        u64 zp1 = pk2(z1A, z1B);

        // 30 packed accumulators: (pointA, pointB)
        u64 Jp[6][2], Bp[6][3];
        #pragma unroll
        for (int i = 0; i < 6; i++) {
            Jp[i][0] = 0ull; Jp[i][1] = 0ull;
            Bp[i][0] = 0ull; Bp[i][1] = 0ull; Bp[i][2] = 0ull;
        }

        for (int t2 = 0; t2 < HIDN / 2; t2++) {
            const int j0 = 2 * t2;

            // --- activation for 2 j's, packed over the 2 points ---
            u64 dp[2], e0p[2], e1p[2], pu0[2], pu1[2];
            #pragma unroll
            for (int q = 0; q < 2; q++) {
                const int j = j0 + q;
                ulonglong2 t0 = sDup[j][0];
                pu0[q] = t0.x; pu1[q] = t0.y;
                u64 ap = fma2(zp0, pu0[q], fma2(zp1, pu1[q], sB[j]));
                float aA, aB;
                upk2(ap, aA, aB);
                float sigA = __fdividef(1.f, 1.f + __expf(-aA));
                float sigB = __fdividef(1.f, 1.f + __expf(-aB));
                u64 sigp = pk2(sigA, sigB);
                u64 omsp = fma2(sigp, NONE2, ONE2);      // 1 - sig
                u64 t1p  = mul2(sigp, omsp);             // sig*(1-sig)
                dp[q]    = fma2(ap, t1p, sigp);          // swish'
                u64 in1  = fma2(sigp, NTWO2, ONE2);      // 1-2sig
                u64 in2  = fma2(ap, in1, TWO2);          // 2 + a(1-2sig)
                u64 ep   = mul2(t1p, in2);               // swish''
                e0p[q]   = mul2(ep, pu0[q]);
                e1p[q]   = mul2(ep, pu1[q]);
            }

            // --- packed accumulation: 30 FFMA2 per j (60 MACs) ---
            #pragma unroll
            for (int q = 0; q < 2; q++) {
                const int j = j0 + q;
                const u64 dq = dp[q], e0 = e0p[q], e1 = e1p[q];
                #pragma unroll
                for (int i = 0; i < 6; i++) {
                    ulonglong2 pi = sDup[j][1 + i];      // (wi*u0,)x2, (wi*u1,)x2
                    Jp[i][0] = fma2(pi.x, dq, Jp[i][0]);
                    Jp[i][1] = fma2(pi.y, dq, Jp[i][1]);
                    Bp[i][0] = fma2(pi.x, e0, Bp[i][0]);
                    Bp[i][1] = fma2(pi.x, e1, Bp[i][1]);
                    Bp[i][2] = fma2(pi.y, e1, Bp[i][2]);
                }
            }
        }

        // Unpack to per-point moments and run the scalar geometry epilogue
        float JA[6][2], BA[6][3], JB[6][2], BB[6][3];
        #pragma unroll
        for (int i = 0; i < 6; i++) {
            upk2(Jp[i][0], JA[i][0], JB[i][0]);
            upk2(Jp[i][1], JA[i][1], JB[i][1]);
            upk2(Bp[i][0], BA[i][0], BB[i][0]);
            upk2(Bp[i][1], BA[i][1], BB[i][1]);
            upk2(Bp[i][2], BA[i][2], BB[i][2]);
        }

        geom_update(JA, BA, sqdtA, nzA.x, nzA.y, z0A, z1A);
        geom_update(JB, BB, sqdtB, nzB.x, nzB.y, z0B, z1B);
    }

    // Final decoder heads for both points
    float muA[3] = { bdmu[0], bdmu[1], bdmu[2] };
    float lsA[3] = { bds[0],  bds[1],  bds[2]  };
    float muB[3] = { bdmu[0], bdmu[1], bdmu[2] };
    float lsB[3] = { bds[0],  bds[1],  bds[2]  };
    #pragma unroll 2
    for (int j = 0; j < HIDN; j++) {
        const float4 A  = tAct[j];
        const float4 wa = tWa[j];
        const float2 wb = tWb[j];
        float aA  = fmaf(z0A, A.x, fmaf(z1A, A.y, A.z));
        float aB  = fmaf(z0B, A.x, fmaf(z1B, A.y, A.z));
        float hA  = aA * __fdividef(1.f, 1.f + __expf(-aA));
        float hB  = aB * __fdividef(1.f, 1.f + __expf(-aB));
        muA[0] = fmaf(hA, wa.x, muA[0]); muB[0] = fmaf(hB, wa.x, muB[0]);
        muA[1] = fmaf(hA, wa.y, muA[1]); muB[1] = fmaf(hB, wa.y, muB[1]);
        muA[2] = fmaf(hA, wa.z, muA[2]); muB[2] = fmaf(hB, wa.z, muB[2]);
        lsA[0] = fmaf(hA, wa.w, lsA[0]); lsB[0] = fmaf(hB, wa.w, lsB[0]);
        lsA[1] = fmaf(hA, wb.x, lsA[1]); lsB[1] = fmaf(hB, wb.x, lsB[1]);
        lsA[2] = fmaf(hA, wb.y, lsA[2]); lsB[2] = fmaf(hB, wb.y, lsB[2]);
    }

    // Outputs: z | mu_xz | log_sigma_xz | mu_zx | log_t_zx | mu_z | log_t_z
    out[2 * pA + 0] = z0A;  out[2 * pA + 1] = z1A;
    out[2 * pB + 0] = z0B;  out[2 * pB + 1] = z1B;
    out[2 * NP + 3 * pA + 0] = muA[0];
    out[2 * NP + 3 * pA + 1] = muA[1];
    out[2 * NP + 3 * pA + 2] = muA[2];
    out[2 * NP + 3 * pB + 0] = muB[0];
    out[2 * NP + 3 * pB + 1] = muB[1];
    out[2 * NP + 3 * pB + 2] = muB[2];
    out[5 * NP + 3 * pA + 0] = lsA[0];
    out[5 * NP + 3 * pA + 1] = lsA[1];
    out[5 * NP + 3 * pA + 2] = lsA[2];
    out[5 * NP + 3 * pB + 0] = lsB[0];
    out[5 * NP + 3 * pB + 1] = lsB[1];
    out[5 * NP + 3 * pB + 2] = lsB[2];
    out[11 * NP + 2 * pA + 0] = b_muz[0];
    out[11 * NP + 2 * pA + 1] = b_muz[1];
    out[11 * NP + 2 * pB + 0] = b_muz[0];
    out[11 * NP + 2 * pB + 1] = b_muz[1];
    out[13 * NP + pA] = b_ltz[0];
    out[13 * NP + pB] = b_ltz[0];
}

extern "C" void kernel_launch(void* const* d_in, const int* in_sizes, int n_in,
                              void* d_out, int out_size)
{
    const float* x     = (const float*)d_in[0];
    const float* We1   = (const float*)d_in[1];
    const float* be1   = (const float*)d_in[2];
    const float* We2   = (const float*)d_in[3];
    const float* be2   = (const float*)d_in[4];
    const float* Wmu   = (const float*)d_in[5];
    const float* bmu   = (const float*)d_in[6];
    const float* Wlt   = (const float*)d_in[7];
    const float* blt   = (const float*)d_in[8];
    const float* Wd1   = (const float*)d_in[9];
    const float* bd1   = (const float*)d_in[10];
    const float* Wdmu  = (const float*)d_in[11];
    const float* bdmu  = (const float*)d_in[12];
    const float* Wds   = (const float*)d_in[13];
    const float* bds   = (const float*)d_in[14];
    const float* b_muz = (const float*)d_in[15];
    const float* b_ltz = (const float*)d_in[16];
    const float* noise = (const float*)d_in[17];
    float* out = (float*)d_out;

    const size_t smem = (size_t)(10800 + 128 * (HIDN + 1)) * sizeof(float); // ~94.9 KB
    cudaFuncSetAttribute(encoder_kernel,
                         cudaFuncAttributeMaxDynamicSharedMemorySize, (int)smem);

    encoder_kernel<<<NP / 128, 128, smem>>>(x, We1, be1, We2, be2,
                                            Wmu, bmu, Wlt, blt, out);
    // 2 points/thread: 64 threads cover 128 points -> 256 blocks
    sde_kernel<<<NP / 128, 64>>>(Wd1, bd1, Wdmu, bdmu, Wds, bds,
                                 b_muz, b_ltz, noise, out);
}